// round 6
// baseline (speedup 1.0000x reference)
#include <cuda_runtime.h>

// FusedMultiPool: out[b,s,h,w] = max_k x[b, idx[s,k], h, w]
// x[32,256,64,64] f32, idx[128,8] i32, out[32,128,64,64] f32.
//
// R5 strategy: direct global gather through L1. CTA = (batch, 32-float hw
// strip). Each channel row of the strip is exactly one 128B L1 line, owned by
// exactly one CTA -> first touch goes to DRAM once (134 MB total), the ~3
// other referencing sets hit L1. No smem staging (removes STS + staging-LDG
// wavefronts that made R4 L1-bound at 75.6%).

#define BB 32
#define CC 256
#define HWP 4096          // 64*64
#define SS 128
#define KK 8
#define TT 32             // hw strip width (floats) == one 128B line per channel
#define NTHREADS 256
#define NWARPS (NTHREADS / 32)
#define SETS_PER_WARP (SS / NWARPS)   // 16

__global__ __launch_bounds__(NTHREADS)
void fmp_kernel(const float* __restrict__ x,
                const int*   __restrict__ idx,
                float*       __restrict__ out)
{
    __shared__ int4 sidx[SS * 2];   // 4 KB: idx table as int4 pairs

    const int b   = blockIdx.y;
    const int hw0 = blockIdx.x * TT;
    const int t   = threadIdx.x;

    // Stage index table (1024 ints = 256 int4)
    {
        const int4* gidx = reinterpret_cast<const int4*>(idx);
        #pragma unroll
        for (int i = t; i < SS * 2; i += NTHREADS)
            sidx[i] = gidx[i];
    }
    __syncthreads();

    const int lane = t & 31;
    const int warp = t >> 5;

    // Base pointer for this (b, strip, lane): all gathers are base + c*HWP.
    const float* __restrict__ xb =
        x + (size_t)b * CC * HWP + hw0 + lane;
    float* __restrict__ outb =
        out + (size_t)b * SS * HWP + hw0 + lane;

    #pragma unroll
    for (int it = 0; it < SETS_PER_WARP; ++it) {
        const int s = warp * SETS_PER_WARP + it;

        // 8 channel indices for this set: two uniform LDS.128 (2 wavefronts)
        const int4 r0 = sidx[s * 2 + 0];
        const int4 r1 = sidx[s * 2 + 1];

        // Issue all 8 gathers before reducing (MLP=8 per set, per warp).
        float v0 = __ldg(xb + (size_t)r0.x * HWP);
        float v1 = __ldg(xb + (size_t)r0.y * HWP);
        float v2 = __ldg(xb + (size_t)r0.z * HWP);
        float v3 = __ldg(xb + (size_t)r0.w * HWP);
        float v4 = __ldg(xb + (size_t)r1.x * HWP);
        float v5 = __ldg(xb + (size_t)r1.y * HWP);
        float v6 = __ldg(xb + (size_t)r1.z * HWP);
        float v7 = __ldg(xb + (size_t)r1.w * HWP);

        float m01 = fmaxf(v0, v1);
        float m23 = fmaxf(v2, v3);
        float m45 = fmaxf(v4, v5);
        float m67 = fmaxf(v6, v7);
        float m   = fmaxf(fmaxf(m01, m23), fmaxf(m45, m67));

        outb[(size_t)s * HWP] = m;   // 128 B coalesced store per warp
    }
}

extern "C" void kernel_launch(void* const* d_in, const int* in_sizes, int n_in,
                              void* d_out, int out_size)
{
    const float* x   = (const float*)d_in[0];   // [32,256,64,64] f32
    const int*   idx = (const int*)d_in[1];     // [128,8] i32
    float*       out = (float*)d_out;           // [32,128,64,64] f32

    dim3 grid(HWP / TT, BB);   // (128, 32) = 4096 CTAs
    fmp_kernel<<<grid, NTHREADS>>>(x, idx, out);
}

// round 7
// speedup vs baseline: 1.0090x; 1.0090x over previous
#include <cuda_runtime.h>

// FusedMultiPool: out[b,s,h,w] = max_k x[b, idx[s,k], h, w]
// x[32,256,64,64] f32, idx[128,8] i32, out[32,128,64,64] f32.
//
// R6: back to R4's smem-staging scheme (R5's direct gather was latency-bound),
// widened to TT=64 with 512 threads and float2 compute:
//   - half the instructions per byte (LDS.64 / STG.64 / float4 staging)
//   - one barrier per 2x the work, 2048 CTAs
//   - __launch_bounds__(512,3) -> 48 warps/SM (R4 was reg-capped at 46/57%)
// L1 pipe (the R4 limiter at 75.6%) sees the same bytes but far fewer
// competing issue slots -> push it toward saturation.

#define BB 32
#define CC 256
#define HWP 4096          // 64*64
#define SS 128
#define KK 8
#define TT 64             // hw strip width (floats) per CTA
#define NTHREADS 512
#define NWARPS (NTHREADS / 32)          // 16
#define SETS_PER_WARP (SS / NWARPS)     // 8

#define SMEM_X_BYTES (CC * TT * 4)              // 64 KB
#define SMEM_BYTES   (SMEM_X_BYTES + SS * 2 * 16) // + 4 KB idx (int4)

__global__ void __launch_bounds__(NTHREADS, 3)
fmp_kernel(const float* __restrict__ x,
           const int*   __restrict__ idx,
           float*       __restrict__ out)
{
    extern __shared__ __align__(16) unsigned char smem_raw[];
    float (*sx)[TT] = reinterpret_cast<float (*)[TT]>(smem_raw);
    int4* sidx = reinterpret_cast<int4*>(smem_raw + SMEM_X_BYTES);

    const int b   = blockIdx.y;
    const int hw0 = blockIdx.x * TT;
    const int t   = threadIdx.x;

    // Stage index table: 1024 ints = 256 int4, one per thread (t < 256).
    if (t < SS * 2)
        sidx[t] = reinterpret_cast<const int4*>(idx)[t];

    // Stage x tile: 256 channels x 64 floats = 64 KB, 8 float4 per thread,
    // fully coalesced (row stride 256 B).
    const float4* xb = reinterpret_cast<const float4*>(
        x + (size_t)b * CC * HWP + hw0);
    #pragma unroll
    for (int it = 0; it < (CC * TT / 4) / NTHREADS; ++it) {   // 8
        int i = t + it * NTHREADS;
        int c = i >> 4;          // 16 float4 per channel row
        int q = i & 15;
        float4 v = xb[(size_t)c * (HWP / 4) + q];
        *reinterpret_cast<float4*>(&sx[c][q * 4]) = v;
    }
    __syncthreads();

    // Compute: warp <-> 8 consecutive sets, lane <-> float2 hw pair.
    const int lane = t & 31;
    const int warp = t >> 5;
    float* outb = out + (size_t)b * SS * HWP + hw0 + lane * 2;

    #pragma unroll
    for (int it = 0; it < SETS_PER_WARP; ++it) {
        const int s = warp * SETS_PER_WARP + it;

        const int4 r0 = sidx[s * 2 + 0];   // broadcast (conflict-free)
        const int4 r1 = sidx[s * 2 + 1];

        // 8 LDS.64 gathers, conflict-free (lane*8B within 256B row).
        float2 v0 = *reinterpret_cast<const float2*>(&sx[r0.x][lane * 2]);
        float2 v1 = *reinterpret_cast<const float2*>(&sx[r0.y][lane * 2]);
        float2 v2 = *reinterpret_cast<const float2*>(&sx[r0.z][lane * 2]);
        float2 v3 = *reinterpret_cast<const float2*>(&sx[r0.w][lane * 2]);
        float2 v4 = *reinterpret_cast<const float2*>(&sx[r1.x][lane * 2]);
        float2 v5 = *reinterpret_cast<const float2*>(&sx[r1.y][lane * 2]);
        float2 v6 = *reinterpret_cast<const float2*>(&sx[r1.z][lane * 2]);
        float2 v7 = *reinterpret_cast<const float2*>(&sx[r1.w][lane * 2]);

        float2 m;
        m.x = fmaxf(fmaxf(fmaxf(v0.x, v1.x), fmaxf(v2.x, v3.x)),
                    fmaxf(fmaxf(v4.x, v5.x), fmaxf(v6.x, v7.x)));
        m.y = fmaxf(fmaxf(fmaxf(v0.y, v1.y), fmaxf(v2.y, v3.y)),
                    fmaxf(fmaxf(v4.y, v5.y), fmaxf(v6.y, v7.y)));

        // 256 B coalesced store per warp (STG.64).
        *reinterpret_cast<float2*>(outb + (size_t)s * HWP) = m;
    }
}

extern "C" void kernel_launch(void* const* d_in, const int* in_sizes, int n_in,
                              void* d_out, int out_size)
{
    const float* x   = (const float*)d_in[0];   // [32,256,64,64] f32
    const int*   idx = (const int*)d_in[1];     // [128,8] i32
    float*       out = (float*)d_out;           // [32,128,64,64] f32

    static bool attr_set = false;
    if (!attr_set) {
        cudaFuncSetAttribute(fmp_kernel,
                             cudaFuncAttributeMaxDynamicSharedMemorySize,
                             SMEM_BYTES);
        attr_set = true;
    }

    dim3 grid(HWP / TT, BB);   // (64, 32) = 2048 CTAs
    fmp_kernel<<<grid, NTHREADS, SMEM_BYTES>>>(x, idx, out);
}

// round 8
// speedup vs baseline: 1.4384x; 1.4255x over previous
#include <cuda_runtime.h>

// FusedMultiPool: out[b,s,h,w] = max_k x[b, idx[s,k], h, w]
// x[32,256,64,64] f32, idx[128,8] i32, out[32,128,64,64] f32.
//
// R7: triple-buffered cp.async pipeline. R4-R6 post-mortem: the limiter is
// DRAM latency exposed at the staging->barrier->compute boundary (issue% fell
// to 20% in R5/R6). Here each CTA owns ~14 tiles; while tile i is computed
// from smem, tiles i+1 and i+2 stream in via cp.async (LDGSTS). One barrier
// per tile. DRAM fill and smem compute overlap fully.

#define BB 32
#define CC 256
#define HWP 4096                 // 64*64
#define SS 128
#define KK 8
#define TT 32                    // hw strip width (floats); one tile = 32 KB
#define NTHREADS 512
#define NWARPS (NTHREADS / 32)   // 16
#define SETS_PER_WARP (SS / NWARPS)  // 8

#define NTILES ((HWP / TT) * BB)     // 4096 flat tiles (b*128 + strip)
#define GRID 296                     // 148 SMs x 2 CTAs
#define TILE_FLOATS (CC * TT)        // 8192
#define TILE_BYTES (TILE_FLOATS * 4) // 32768
#define NBUF 3
#define SMEM_BYTES (NBUF * TILE_BYTES + SS * 2 * 16)  // 96 KB bufs + 4 KB idx

__device__ __forceinline__ void cp_async16(void* smem_dst, const void* gmem_src)
{
    unsigned saddr = (unsigned)__cvta_generic_to_shared(smem_dst);
    asm volatile("cp.async.cg.shared.global [%0], [%1], 16;\n"
                 :: "r"(saddr), "l"(gmem_src));
}
#define CP_COMMIT() asm volatile("cp.async.commit_group;\n" ::: "memory")
#define CP_WAIT1()  asm volatile("cp.async.wait_group 1;\n" ::: "memory")

// Stage one 256x32-float tile (32 KB) into buf: 2048 x 16B chunks,
// 4 chunks per thread, fully coalesced (8 threads cover one 128B channel row).
__device__ __forceinline__ void prefetch_tile(float* buf, const float* __restrict__ x,
                                              int flat, int t)
{
    const int b     = flat >> 7;     // / (HWP/TT)
    const int strip = flat & 127;
    const char* src = reinterpret_cast<const char*>(
        x + (size_t)b * CC * HWP + strip * TT);
    char* dst = reinterpret_cast<char*>(buf);
    #pragma unroll
    for (int j = 0; j < (TILE_BYTES / 16) / NTHREADS; ++j) {   // 4
        int chunk = t + j * NTHREADS;
        int c = chunk >> 3;          // 8 chunks per channel row
        int q = chunk & 7;
        cp_async16(dst + chunk * 16, src + (size_t)c * (HWP * 4) + q * 16);
    }
}

__global__ void __launch_bounds__(NTHREADS, 2)
fmp_kernel(const float* __restrict__ x,
           const int*   __restrict__ idx,
           float*       __restrict__ out)
{
    extern __shared__ __align__(16) unsigned char smem_raw[];
    float* bufs = reinterpret_cast<float*>(smem_raw);                 // 3 tiles
    int4*  sidx = reinterpret_cast<int4*>(smem_raw + NBUF * TILE_BYTES);

    const int t    = threadIdx.x;
    const int lane = t & 31;
    const int warp = t >> 5;
    const int g    = blockIdx.x;

    // Stage index table once (1024 ints = 256 int4); visible after the first
    // in-loop __syncthreads(), which precedes any compute.
    if (t < SS * 2)
        sidx[t] = reinterpret_cast<const int4*>(idx)[t];

    const int n = (NTILES - 1 - g) / GRID + 1;   // 13 or 14 tiles for this CTA

    // Prologue: tiles 0 and 1 in flight.
    prefetch_tile(bufs, x, g, t);
    CP_COMMIT();
    if (n > 1) prefetch_tile(bufs + TILE_FLOATS, x, g + GRID, t);
    CP_COMMIT();

    int cur = 0;                                  // buffer of tile i
    for (int i = 0; i < n; ++i) {
        CP_WAIT1();          // my chunks of tile i have landed (tile i+1 may pend)
        __syncthreads();     // everyone's chunks landed; buf of tile i-1 is free

        // Prefetch tile i+2 into the buffer freed by tile i-1.
        int nxt2 = cur + 2; if (nxt2 >= NBUF) nxt2 -= NBUF;
        if (i + 2 < n)
            prefetch_tile(bufs + nxt2 * TILE_FLOATS, x, g + (i + 2) * GRID, t);
        CP_COMMIT();

        // Compute tile i: warp <-> 8 sets, lane <-> hw position.
        const float* __restrict__ buf = bufs + cur * TILE_FLOATS;
        const int flat  = g + i * GRID;
        const int b     = flat >> 7;
        const int strip = flat & 127;
        float* outb = out + (size_t)b * SS * HWP + strip * TT + lane;

        #pragma unroll
        for (int it = 0; it < SETS_PER_WARP; ++it) {
            const int s = warp * SETS_PER_WARP + it;
            const int4 r0 = sidx[s * 2 + 0];     // broadcast, conflict-free
            const int4 r1 = sidx[s * 2 + 1];

            float v0 = buf[r0.x * TT + lane];
            float v1 = buf[r0.y * TT + lane];
            float v2 = buf[r0.z * TT + lane];
            float v3 = buf[r0.w * TT + lane];
            float v4 = buf[r1.x * TT + lane];
            float v5 = buf[r1.y * TT + lane];
            float v6 = buf[r1.z * TT + lane];
            float v7 = buf[r1.w * TT + lane];

            float m = fmaxf(fmaxf(fmaxf(v0, v1), fmaxf(v2, v3)),
                            fmaxf(fmaxf(v4, v5), fmaxf(v6, v7)));

            outb[(size_t)s * HWP] = m;           // 128 B coalesced STG per warp
        }

        if (++cur == NBUF) cur = 0;
    }
}

extern "C" void kernel_launch(void* const* d_in, const int* in_sizes, int n_in,
                              void* d_out, int out_size)
{
    const float* x   = (const float*)d_in[0];   // [32,256,64,64] f32
    const int*   idx = (const int*)d_in[1];     // [128,8] i32
    float*       out = (float*)d_out;           // [32,128,64,64] f32

    static bool attr_set = false;
    if (!attr_set) {
        cudaFuncSetAttribute(fmp_kernel,
                             cudaFuncAttributeMaxDynamicSharedMemorySize,
                             SMEM_BYTES);
        attr_set = true;
    }

    fmp_kernel<<<GRID, NTHREADS, SMEM_BYTES>>>(x, idx, out);
}